// round 8
// baseline (speedup 1.0000x reference)
#include <cuda_runtime.h>

#define BW    512      // batch windows
#define NTOK  512      // query tokens per window
#define DIMC  192
#define NH    6
#define HD    32
#define PT    64       // permuted kv tokens per window
#define QSCALE 0.17677669529663687f   // 1/sqrt(32)

// ---------------- scratch (static device globals; no runtime allocation) ----
__device__ float g_q[(size_t)BW * NH * NTOK * HD];    // [b][h][n][d]
__device__ float g_k[(size_t)BW * NH * PT * HD];      // [b][h][p][d]
__device__ float g_v[(size_t)BW * NH * PT * HD];      // [b][h][p][d]
__device__ float g_bias[NH * NTOK * PT];              // [h][n][p]
__device__ float g_att[(size_t)BW * NTOK * DIMC];     // [b][n][h*32+d]

// ---------------- kernel 0: gather relative-position bias -------------------
__global__ void bias_gather(const float* __restrict__ table,
                            const int* __restrict__ rpi) {
    int idx = blockIdx.x * 256 + threadIdx.x;
    if (idx >= NH * NTOK * PT) return;
    int h = idx / (NTOK * PT);
    int r = idx - h * (NTOK * PT);            // n*64 + p
    g_bias[idx] = table[rpi[r] * NH + h];
}

// ---------------- kernel 1: fused QKV projection + permuted scatter ---------
// y[262144 x 240] = x[262144 x 192] @ [wq | wkv]
// block tile 128x48, 128 threads, thread tile 16x3.
// x_sh stored k-major -> A fragment = 4x LDS.128 broadcast (conflict-free);
// 7 LDS / 48 FFMA per kk -> FFMA-pipe bound instead of LDS-bound.
__global__ __launch_bounds__(128) void qkv_gemm(
    const float* __restrict__ x,
    const float* __restrict__ wq, const float* __restrict__ bq,
    const float* __restrict__ wkv, const float* __restrict__ bkv)
{
    constexpr int KT = 48;
    __shared__ float x_sh[KT][128];   // [k][r] transposed
    __shared__ float w_sh[KT][52];    // [k][n], pad 52

    int tid = threadIdx.x;
    int mg = tid >> 4;                // 0..7  (16 rows each)
    int ng = tid & 15;                // 0..15 (3 cols each)
    int row0 = blockIdx.x * 128;
    int col0 = blockIdx.y * 48;

    float acc[16][3];
#pragma unroll
    for (int i = 0; i < 16; i++)
#pragma unroll
        for (int j = 0; j < 3; j++) acc[i][j] = 0.f;

    for (int kt = 0; kt < 4; kt++) {
        int k0 = kt * KT;
        if (kt) __syncthreads();

        // ---- X tile: 128 rows x 48 k = 1536 float4, 12 per thread ----------
#pragma unroll
        for (int i = 0; i < 12; i++) {
            int f = tid + i * 128;
            int r = f / 12, c4 = (f % 12) * 4;
            float4 v = *(const float4*)(x + (size_t)(row0 + r) * DIMC + k0 + c4);
            x_sh[c4 + 0][r] = v.x;
            x_sh[c4 + 1][r] = v.y;
            x_sh[c4 + 2][r] = v.z;
            x_sh[c4 + 3][r] = v.w;
        }
        // ---- W tile: 48 k x 48 n, 18 floats per thread ---------------------
#pragma unroll
        for (int i = 0; i < 18; i++) {
            int idx = tid + i * 128;
            int k = idx / 48, n = idx - (idx / 48) * 48;
            int c = col0 + n;
            w_sh[k][n] = (c < 192) ? wq[(k0 + k) * 192 + c]
                                   : wkv[(k0 + k) * 48 + (c - 192)];
        }
        __syncthreads();

#pragma unroll 12
        for (int kk = 0; kk < KT; kk++) {
            float4 a0 = *(const float4*)&x_sh[kk][mg * 16];
            float4 a1 = *(const float4*)&x_sh[kk][mg * 16 + 4];
            float4 a2 = *(const float4*)&x_sh[kk][mg * 16 + 8];
            float4 a3 = *(const float4*)&x_sh[kk][mg * 16 + 12];
            float b0 = w_sh[kk][ng * 3];
            float b1 = w_sh[kk][ng * 3 + 1];
            float b2 = w_sh[kk][ng * 3 + 2];
            float av[16] = {a0.x, a0.y, a0.z, a0.w, a1.x, a1.y, a1.z, a1.w,
                            a2.x, a2.y, a2.z, a2.w, a3.x, a3.y, a3.z, a3.w};
#pragma unroll
            for (int i = 0; i < 16; i++) {
                acc[i][0] = fmaf(av[i], b0, acc[i][0]);
                acc[i][1] = fmaf(av[i], b1, acc[i][1]);
                acc[i][2] = fmaf(av[i], b2, acc[i][2]);
            }
        }
    }

    // ---- epilogue: Q scale+store / permuted KV scatter ----
#pragma unroll
    for (int i = 0; i < 16; i++) {
        int row = row0 + mg * 16 + i;
        int b = row >> 9, n = row & 511;
#pragma unroll
        for (int j = 0; j < 3; j++) {
            int c = col0 + ng * 3 + j;
            float v = acc[i][j];
            if (c < 192) {                       // Q path
                v = (v + bq[c]) * QSCALE;
                int head = c >> 5, d = c & 31;
                g_q[(((size_t)b * NH + head) * NTOK + n) * HD + d] = v;
            } else {                             // KV path: permuted scatter
                int c4 = c - 192;
                v = v + bkv[c4];
                int D = n >> 6, H = (n >> 3) & 7, W = n & 7;
                int p  = ((D >> 1) << 4) + ((H >> 1) << 2) + (W >> 1);
                int c2 = (H & 1) * 96 + (W & 1) * 48 + c4;
                int head = c2 >> 5, d = c2 & 31;
                size_t dst = (((size_t)b * NH + head) * PT + p) * HD + d;
                if ((D & 1) == 0) g_k[dst] = v;
                else              g_v[dst] = v;
            }
        }
    }
}

// ---------------- kernel 2: attention (1 thread = 1 query row) --------------
__global__ __launch_bounds__(128) void attn_kernel() {
    int bh = blockIdx.x;                 // b*6 + h
    int h  = bh % NH;
    int b  = bh / NH;
    int n  = blockIdx.y * 128 + threadIdx.x;

    __shared__ float4 k4[PT * 8];
    __shared__ float4 v4[PT * 8];
    const float4* gk = (const float4*)(g_k + (size_t)bh * PT * HD);
    const float4* gv = (const float4*)(g_v + (size_t)bh * PT * HD);
    for (int i = threadIdx.x; i < PT * 8; i += 128) { k4[i] = gk[i]; v4[i] = gv[i]; }

    float4 q[8];
    const float4* gq = (const float4*)(g_q + ((size_t)bh * NTOK + n) * HD);
#pragma unroll
    for (int i = 0; i < 8; i++) q[i] = gq[i];

    float sc[64];
    const float4* brow = (const float4*)(g_bias + ((size_t)h * NTOK + n) * PT);
#pragma unroll
    for (int i = 0; i < 16; i++) {
        float4 bb = brow[i];
        sc[4 * i + 0] = bb.x; sc[4 * i + 1] = bb.y;
        sc[4 * i + 2] = bb.z; sc[4 * i + 3] = bb.w;
    }
    __syncthreads();

    float m = -1e30f;
#pragma unroll
    for (int p = 0; p < 64; p++) {
        float s = sc[p];
#pragma unroll
        for (int d = 0; d < 8; d++) {
            float4 kk = k4[p * 8 + d];           // broadcast LDS.128
            s += q[d].x * kk.x + q[d].y * kk.y + q[d].z * kk.z + q[d].w * kk.w;
        }
        sc[p] = s;
        m = fmaxf(m, s);
    }
    float sum = 0.f;
#pragma unroll
    for (int p = 0; p < 64; p++) { float e = __expf(sc[p] - m); sc[p] = e; sum += e; }

    float4 acc[8];
#pragma unroll
    for (int d = 0; d < 8; d++) acc[d] = make_float4(0.f, 0.f, 0.f, 0.f);
#pragma unroll
    for (int p = 0; p < 64; p++) {
        float pr = sc[p];
#pragma unroll
        for (int d = 0; d < 8; d++) {
            float4 vv = v4[p * 8 + d];           // broadcast LDS.128
            acc[d].x = fmaf(pr, vv.x, acc[d].x);
            acc[d].y = fmaf(pr, vv.y, acc[d].y);
            acc[d].z = fmaf(pr, vv.z, acc[d].z);
            acc[d].w = fmaf(pr, vv.w, acc[d].w);
        }
    }
    float inv = 1.f / sum;
    float4* orow = (float4*)(g_att + ((size_t)(b * NTOK + n)) * DIMC + h * HD);
#pragma unroll
    for (int d = 0; d < 8; d++) {
        acc[d].x *= inv; acc[d].y *= inv; acc[d].z *= inv; acc[d].w *= inv;
        orow[d] = acc[d];
    }
}

// ---------------- kernel 3: output projection -------------------------------
__global__ __launch_bounds__(128) void proj_gemm(
    const float* __restrict__ wproj, const float* __restrict__ bproj,
    float* __restrict__ out)
{
    constexpr int KT = 48;
    __shared__ float x_sh[KT][128];   // [k][r] transposed
    __shared__ float w_sh[KT][52];    // [k][n], pad 52

    int tid = threadIdx.x;
    int mg = tid >> 4;
    int ng = tid & 15;
    int row0 = blockIdx.x * 128;
    int col0 = blockIdx.y * 48;

    float acc[16][3];
#pragma unroll
    for (int i = 0; i < 16; i++)
#pragma unroll
        for (int j = 0; j < 3; j++) acc[i][j] = 0.f;

    for (int kt = 0; kt < 4; kt++) {
        int k0 = kt * KT;
        if (kt) __syncthreads();

#pragma unroll
        for (int i = 0; i < 12; i++) {
            int f = tid + i * 128;
            int r = f / 12, c4 = (f % 12) * 4;
            float4 v = *(const float4*)(g_att + (size_t)(row0 + r) * DIMC + k0 + c4);
            x_sh[c4 + 0][r] = v.x;
            x_sh[c4 + 1][r] = v.y;
            x_sh[c4 + 2][r] = v.z;
            x_sh[c4 + 3][r] = v.w;
        }
#pragma unroll
        for (int i = 0; i < 18; i++) {
            int idx = tid + i * 128;
            int k = idx / 48, n = idx - (idx / 48) * 48;
            w_sh[k][n] = wproj[(k0 + k) * 192 + col0 + n];
        }
        __syncthreads();

#pragma unroll 12
        for (int kk = 0; kk < KT; kk++) {
            float4 a0 = *(const float4*)&x_sh[kk][mg * 16];
            float4 a1 = *(const float4*)&x_sh[kk][mg * 16 + 4];
            float4 a2 = *(const float4*)&x_sh[kk][mg * 16 + 8];
            float4 a3 = *(const float4*)&x_sh[kk][mg * 16 + 12];
            float b0 = w_sh[kk][ng * 3];
            float b1 = w_sh[kk][ng * 3 + 1];
            float b2 = w_sh[kk][ng * 3 + 2];
            float av[16] = {a0.x, a0.y, a0.z, a0.w, a1.x, a1.y, a1.z, a1.w,
                            a2.x, a2.y, a2.z, a2.w, a3.x, a3.y, a3.z, a3.w};
#pragma unroll
            for (int i = 0; i < 16; i++) {
                acc[i][0] = fmaf(av[i], b0, acc[i][0]);
                acc[i][1] = fmaf(av[i], b1, acc[i][1]);
                acc[i][2] = fmaf(av[i], b2, acc[i][2]);
            }
        }
    }

#pragma unroll
    for (int i = 0; i < 16; i++) {
        size_t row = row0 + mg * 16 + i;
#pragma unroll
        for (int j = 0; j < 3; j++) {
            int c = col0 + ng * 3 + j;
            out[row * DIMC + c] = acc[i][j] + bproj[c];
        }
    }
}

// ---------------- launch ----------------------------------------------------
extern "C" void kernel_launch(void* const* d_in, const int* in_sizes, int n_in,
                              void* d_out, int out_size) {
    const float* x     = (const float*)d_in[0];
    const float* wq    = (const float*)d_in[1];
    const float* bq    = (const float*)d_in[2];
    const float* wkv   = (const float*)d_in[3];
    const float* bkv   = (const float*)d_in[4];
    const float* table = (const float*)d_in[5];
    const float* wproj = (const float*)d_in[6];
    const float* bproj = (const float*)d_in[7];
    const int*   rpi   = (const int*)d_in[8];
    float* out = (float*)d_out;

    bias_gather<<<(NH * NTOK * PT + 255) / 256, 256>>>(table, rpi);
    qkv_gemm<<<dim3(2048, 5), 128>>>(x, wq, bq, wkv, bkv);
    attn_kernel<<<dim3(BW * NH, 4), 128>>>();
    proj_gemm<<<dim3(2048, 4), 128>>>(wproj, bproj, out);
}

// round 9
// speedup vs baseline: 1.2551x; 1.2551x over previous
#include <cuda_runtime.h>

#define BW    512      // batch windows
#define NTOK  512      // query tokens per window
#define DIMC  192
#define NH    6
#define HD    32
#define PT    64       // permuted kv tokens per window
#define QSCALE 0.17677669529663687f   // 1/sqrt(32)

// ---------------- scratch (static device globals; no runtime allocation) ----
__device__ float g_q[(size_t)BW * NH * NTOK * HD];    // [b][h][n][d]
__device__ float g_k[(size_t)BW * NH * PT * HD];      // [b][h][p][d]
__device__ float g_v[(size_t)BW * NH * PT * HD];      // [b][h][p][d]
__device__ float g_bias[NH * NTOK * PT];              // [h][n][p]
__device__ float g_att[(size_t)BW * NTOK * DIMC];     // [b][n][h*32+d]

// ---------------- kernel 0: gather relative-position bias -------------------
__global__ void bias_gather(const float* __restrict__ table,
                            const int* __restrict__ rpi) {
    int idx = blockIdx.x * 256 + threadIdx.x;
    if (idx >= NH * NTOK * PT) return;
    int h = idx / (NTOK * PT);
    int r = idx - h * (NTOK * PT);            // n*64 + p
    g_bias[idx] = table[rpi[r] * NH + h];
}

// ---------------- kernel 1: fused QKV projection + permuted scatter ---------
// y[262144 x 240] = x[262144 x 192] @ [wq | wkv]
// block 128x64 (grid.y=4, cols >=240 masked), 256 threads, thread tile 8x4.
// A: LDS.128 along k from row-major x_sh (no transpose). Interleaved thread
// rows (m = mg + 16*i) keep the two mg's per warp on distinct bank-quads.
// B: LDS.128 along n. Mainloop ~24 LDS-wf per 128 FFMA-instr -> FFMA-bound.
__global__ __launch_bounds__(256) void qkv_gemm(
    const float* __restrict__ x,
    const float* __restrict__ wq, const float* __restrict__ bq,
    const float* __restrict__ wkv, const float* __restrict__ bkv)
{
    constexpr int KT = 48;
    __shared__ float x_sh[128][52];   // [m][k], pitch 52 (13 quads)
    __shared__ float w_sh[KT][68];    // [k][n], pitch 68 (17 quads)

    int tid = threadIdx.x;
    int w   = tid >> 5, l = tid & 31;
    int mg  = tid >> 4;               // 0..15: thread rows = mg + 16*i
    int ng  = tid & 15;               // 0..15: thread cols = ng*4 .. +3
    int row0 = blockIdx.x * 128;
    int col0 = blockIdx.y * 64;

    float acc[8][4];
#pragma unroll
    for (int i = 0; i < 8; i++)
#pragma unroll
        for (int j = 0; j < 4; j++) acc[i][j] = 0.f;

    for (int kt = 0; kt < 4; kt++) {
        int k0 = kt * KT;
        if (kt) __syncthreads();

        // ---- X tile: 128 x 48, warp-structured (8 rows x 4 k-chunks/lane) --
#pragma unroll
        for (int i = 0; i < 6; i++) {
            int r  = w * 16 + (i & 1) * 8 + (l >> 2);
            int kc = (i >> 1) * 16 + (l & 3) * 4;
            float4 v = *(const float4*)(x + (size_t)(row0 + r) * DIMC + k0 + kc);
            *(float4*)&x_sh[r][kc] = v;
        }
        // ---- W tile: 48 k x 64 n (float4 per lane) -------------------------
#pragma unroll
        for (int i = 0; i < 3; i++) {
            int f = tid + 256 * i;
            int k = f >> 4, cq = f & 15;
            float4 v;
            if (col0 < 192) {                    // pure-Q column blocks
                v = *(const float4*)(wq + (size_t)(k0 + k) * 192 + col0 + cq * 4);
            } else {                             // KV block (cols 192..255)
                if (cq < 12)
                    v = *(const float4*)(wkv + (size_t)(k0 + k) * 48 + cq * 4);
                else
                    v = make_float4(0.f, 0.f, 0.f, 0.f);
            }
            *(float4*)&w_sh[k][cq * 4] = v;
        }
        __syncthreads();

        // ---- mainloop: 12 x (4-kk) steps ----
        for (int kkb = 0; kkb < 12; kkb++) {
            float4 a[8];
#pragma unroll
            for (int i = 0; i < 8; i++)
                a[i] = *(const float4*)&x_sh[mg + 16 * i][kkb * 4];
#pragma unroll
            for (int kk = 0; kk < 4; kk++) {
                float4 b = *(const float4*)&w_sh[kkb * 4 + kk][ng * 4];
#pragma unroll
                for (int i = 0; i < 8; i++) {
                    float av = (kk == 0) ? a[i].x : (kk == 1) ? a[i].y
                             : (kk == 2) ? a[i].z : a[i].w;
                    acc[i][0] = fmaf(av, b.x, acc[i][0]);
                    acc[i][1] = fmaf(av, b.y, acc[i][1]);
                    acc[i][2] = fmaf(av, b.z, acc[i][2]);
                    acc[i][3] = fmaf(av, b.w, acc[i][3]);
                }
            }
        }
    }

    // ---- epilogue: Q scale+store / permuted KV scatter ----
#pragma unroll
    for (int i = 0; i < 8; i++) {
        int row = row0 + mg + 16 * i;
        int b = row >> 9, n = row & 511;
#pragma unroll
        for (int j = 0; j < 4; j++) {
            int c = col0 + ng * 4 + j;
            if (c >= 240) continue;
            float v = acc[i][j];
            if (c < 192) {                       // Q path
                v = (v + bq[c]) * QSCALE;
                int head = c >> 5, d = c & 31;
                g_q[(((size_t)b * NH + head) * NTOK + n) * HD + d] = v;
            } else {                             // KV path: permuted scatter
                int c4 = c - 192;
                v = v + bkv[c4];
                int D = n >> 6, H = (n >> 3) & 7, W = n & 7;
                int p  = ((D >> 1) << 4) + ((H >> 1) << 2) + (W >> 1);
                int c2 = (H & 1) * 96 + (W & 1) * 48 + c4;
                int head = c2 >> 5, d = c2 & 31;
                size_t dst = (((size_t)b * NH + head) * PT + p) * HD + d;
                if ((D & 1) == 0) g_k[dst] = v;
                else              g_v[dst] = v;
            }
        }
    }
}

// ---------------- kernel 2: attention (1 thread = 1 query row) --------------
__global__ __launch_bounds__(128) void attn_kernel() {
    int bh = blockIdx.x;                 // b*6 + h
    int h  = bh % NH;
    int b  = bh / NH;
    int n  = blockIdx.y * 128 + threadIdx.x;

    __shared__ float4 k4[PT * 8];
    __shared__ float4 v4[PT * 8];
    const float4* gk = (const float4*)(g_k + (size_t)bh * PT * HD);
    const float4* gv = (const float4*)(g_v + (size_t)bh * PT * HD);
    for (int i = threadIdx.x; i < PT * 8; i += 128) { k4[i] = gk[i]; v4[i] = gv[i]; }

    float4 q[8];
    const float4* gq = (const float4*)(g_q + ((size_t)bh * NTOK + n) * HD);
#pragma unroll
    for (int i = 0; i < 8; i++) q[i] = gq[i];

    float sc[64];
    const float4* brow = (const float4*)(g_bias + ((size_t)h * NTOK + n) * PT);
#pragma unroll
    for (int i = 0; i < 16; i++) {
        float4 bb = brow[i];
        sc[4 * i + 0] = bb.x; sc[4 * i + 1] = bb.y;
        sc[4 * i + 2] = bb.z; sc[4 * i + 3] = bb.w;
    }
    __syncthreads();

    float m = -1e30f;
#pragma unroll
    for (int p = 0; p < 64; p++) {
        float s = sc[p];
#pragma unroll
        for (int d = 0; d < 8; d++) {
            float4 kk = k4[p * 8 + d];           // broadcast LDS.128
            s += q[d].x * kk.x + q[d].y * kk.y + q[d].z * kk.z + q[d].w * kk.w;
        }
        sc[p] = s;
        m = fmaxf(m, s);
    }
    float sum = 0.f;
#pragma unroll
    for (int p = 0; p < 64; p++) { float e = __expf(sc[p] - m); sc[p] = e; sum += e; }

    float4 acc[8];
#pragma unroll
    for (int d = 0; d < 8; d++) acc[d] = make_float4(0.f, 0.f, 0.f, 0.f);
#pragma unroll
    for (int p = 0; p < 64; p++) {
        float pr = sc[p];
#pragma unroll
        for (int d = 0; d < 8; d++) {
            float4 vv = v4[p * 8 + d];           // broadcast LDS.128
            acc[d].x = fmaf(pr, vv.x, acc[d].x);
            acc[d].y = fmaf(pr, vv.y, acc[d].y);
            acc[d].z = fmaf(pr, vv.z, acc[d].z);
            acc[d].w = fmaf(pr, vv.w, acc[d].w);
        }
    }
    float inv = 1.f / sum;
    float4* orow = (float4*)(g_att + ((size_t)(b * NTOK + n)) * DIMC + h * HD);
#pragma unroll
    for (int d = 0; d < 8; d++) {
        acc[d].x *= inv; acc[d].y *= inv; acc[d].z *= inv; acc[d].w *= inv;
        orow[d] = acc[d];
    }
}

// ---------------- kernel 3: output projection -------------------------------
__global__ __launch_bounds__(256) void proj_gemm(
    const float* __restrict__ wproj, const float* __restrict__ bproj,
    float* __restrict__ out)
{
    constexpr int KT = 48;
    __shared__ float x_sh[128][52];
    __shared__ float w_sh[KT][68];

    int tid = threadIdx.x;
    int w   = tid >> 5, l = tid & 31;
    int mg  = tid >> 4;
    int ng  = tid & 15;
    int row0 = blockIdx.x * 128;
    int col0 = blockIdx.y * 64;

    float acc[8][4];
#pragma unroll
    for (int i = 0; i < 8; i++)
#pragma unroll
        for (int j = 0; j < 4; j++) acc[i][j] = 0.f;

    for (int kt = 0; kt < 4; kt++) {
        int k0 = kt * KT;
        if (kt) __syncthreads();

#pragma unroll
        for (int i = 0; i < 6; i++) {
            int r  = w * 16 + (i & 1) * 8 + (l >> 2);
            int kc = (i >> 1) * 16 + (l & 3) * 4;
            float4 v = *(const float4*)(g_att + (size_t)(row0 + r) * DIMC + k0 + kc);
            *(float4*)&x_sh[r][kc] = v;
        }
#pragma unroll
        for (int i = 0; i < 3; i++) {
            int f = tid + 256 * i;
            int k = f >> 4, cq = f & 15;
            float4 v = *(const float4*)(wproj + (size_t)(k0 + k) * 192 + col0 + cq * 4);
            *(float4*)&w_sh[k][cq * 4] = v;
        }
        __syncthreads();

        for (int kkb = 0; kkb < 12; kkb++) {
            float4 a[8];
#pragma unroll
            for (int i = 0; i < 8; i++)
                a[i] = *(const float4*)&x_sh[mg + 16 * i][kkb * 4];
#pragma unroll
            for (int kk = 0; kk < 4; kk++) {
                float4 b = *(const float4*)&w_sh[kkb * 4 + kk][ng * 4];
#pragma unroll
                for (int i = 0; i < 8; i++) {
                    float av = (kk == 0) ? a[i].x : (kk == 1) ? a[i].y
                             : (kk == 2) ? a[i].z : a[i].w;
                    acc[i][0] = fmaf(av, b.x, acc[i][0]);
                    acc[i][1] = fmaf(av, b.y, acc[i][1]);
                    acc[i][2] = fmaf(av, b.z, acc[i][2]);
                    acc[i][3] = fmaf(av, b.w, acc[i][3]);
                }
            }
        }
    }

    // ---- epilogue: vectorized store with bias ----
    int cb = col0 + ng * 4;
    float4 bias = *(const float4*)(bproj + cb);
#pragma unroll
    for (int i = 0; i < 8; i++) {
        size_t row = row0 + mg + 16 * i;
        float4 o;
        o.x = acc[i][0] + bias.x;
        o.y = acc[i][1] + bias.y;
        o.z = acc[i][2] + bias.z;
        o.w = acc[i][3] + bias.w;
        *(float4*)(out + row * DIMC + cb) = o;
    }
}

// ---------------- launch ----------------------------------------------------
extern "C" void kernel_launch(void* const* d_in, const int* in_sizes, int n_in,
                              void* d_out, int out_size) {
    const float* x     = (const float*)d_in[0];
    const float* wq    = (const float*)d_in[1];
    const float* bq    = (const float*)d_in[2];
    const float* wkv   = (const float*)d_in[3];
    const float* bkv   = (const float*)d_in[4];
    const float* table = (const float*)d_in[5];
    const float* wproj = (const float*)d_in[6];
    const float* bproj = (const float*)d_in[7];
    const int*   rpi   = (const int*)d_in[8];
    float* out = (float*)d_out;

    bias_gather<<<(NH * NTOK * PT + 255) / 256, 256>>>(table, rpi);
    qkv_gemm<<<dim3(2048, 4), 256>>>(x, wq, bq, wkv, bkv);
    attn_kernel<<<dim3(BW * NH, 4), 128>>>();
    proj_gemm<<<dim3(2048, 3), 256>>>(wproj, bproj, out);
}

// round 11
// speedup vs baseline: 1.2703x; 1.0120x over previous
#include <cuda_runtime.h>

#define BW    512      // batch windows
#define NTOK  512      // query tokens per window
#define DIMC  192
#define NH    6
#define HD    32
#define PT    64       // permuted kv tokens per window
#define QSCALE 0.17677669529663687f   // 1/sqrt(32)

// ---------------- scratch (static device globals; no runtime allocation) ----
__device__ float g_q[(size_t)BW * NH * NTOK * HD];    // [b][h][n][d]
__device__ float g_k[(size_t)BW * NH * PT * HD];      // [b][h][p][d]
__device__ float g_v[(size_t)BW * NH * PT * HD];      // [b][h][p][d]
__device__ float g_bias[NH * NTOK * PT];              // [h][n][p]
__device__ float g_att[(size_t)BW * NTOK * DIMC];     // [b][n][h*32+d]

// ---------------- kernel 0: gather relative-position bias -------------------
__global__ void bias_gather(const float* __restrict__ table,
                            const int* __restrict__ rpi) {
    int idx = blockIdx.x * 256 + threadIdx.x;
    if (idx >= NH * NTOK * PT) return;
    int h = idx / (NTOK * PT);
    int r = idx - h * (NTOK * PT);            // n*64 + p
    g_bias[idx] = table[rpi[r] * NH + h];
}

// ---------------- kernel 1: fused QKV projection + permuted scatter ---------
// y[262144 x 240] = x[262144 x 192] @ [wq | wkv]
// block 128x64 (grid.y=4, cols >=240 masked), 256 threads, thread tile 8x4.
// KT=24, A frags as float2 (2-kk steps): regs ~70 -> 3 blocks/SM (reg-file
// boundary at 85 regs); smem 20.8KB/block so smem never binds.
__global__ __launch_bounds__(256) void qkv_gemm(
    const float* __restrict__ x,
    const float* __restrict__ wq, const float* __restrict__ bq,
    const float* __restrict__ wkv, const float* __restrict__ bkv)
{
    constexpr int KT = 24;
    __shared__ float x_sh[128][28];   // [m][k], pitch 28 (7 quads, odd -> cf)
    __shared__ float w_sh[KT][68];    // [k][n], pitch 68 (17 quads)

    int tid = threadIdx.x;
    int mg  = tid >> 4;               // 0..15: thread rows = mg + 16*i
    int ng  = tid & 15;               // 0..15: thread cols = ng*4 .. +3
    int row0 = blockIdx.x * 128;
    int col0 = blockIdx.y * 64;

    float acc[8][4];
#pragma unroll
    for (int i = 0; i < 8; i++)
#pragma unroll
        for (int j = 0; j < 4; j++) acc[i][j] = 0.f;

    for (int kt = 0; kt < 8; kt++) {
        int k0 = kt * KT;
        if (kt) __syncthreads();

        // ---- X tile: 128 x 24 = 768 float4, 3 per thread -------------------
#pragma unroll
        for (int i = 0; i < 3; i++) {
            int f = tid + i * 256;
            int r = f / 6, q = f % 6;
            float4 v = *(const float4*)(x + (size_t)(row0 + r) * DIMC + k0 + q * 4);
            *(float4*)&x_sh[r][q * 4] = v;
        }
        // ---- W tile: 24 k x 64 n = 384 float4 ------------------------------
#pragma unroll
        for (int i = 0; i < 2; i++) {
            int f = tid + i * 256;
            if (f < 384) {
                int k = f >> 4, cq = f & 15;
                float4 v;
                if (col0 < 192) {                // pure-Q column blocks
                    v = *(const float4*)(wq + (size_t)(k0 + k) * 192 + col0 + cq * 4);
                } else {                         // KV block (cols 192..255)
                    if (cq < 12)
                        v = *(const float4*)(wkv + (size_t)(k0 + k) * 48 + cq * 4);
                    else
                        v = make_float4(0.f, 0.f, 0.f, 0.f);
                }
                *(float4*)&w_sh[k][cq * 4] = v;
            }
        }
        __syncthreads();

        // ---- mainloop: 12 x (2-kk) steps ----
        for (int s = 0; s < 12; s++) {
            float2 a[8];
#pragma unroll
            for (int i = 0; i < 8; i++)
                a[i] = *(const float2*)&x_sh[mg + 16 * i][s * 2];
            float4 b0 = *(const float4*)&w_sh[s * 2][ng * 4];
            float4 b1 = *(const float4*)&w_sh[s * 2 + 1][ng * 4];
#pragma unroll
            for (int i = 0; i < 8; i++) {
                acc[i][0] = fmaf(a[i].x, b0.x, acc[i][0]);
                acc[i][1] = fmaf(a[i].x, b0.y, acc[i][1]);
                acc[i][2] = fmaf(a[i].x, b0.z, acc[i][2]);
                acc[i][3] = fmaf(a[i].x, b0.w, acc[i][3]);
                acc[i][0] = fmaf(a[i].y, b1.x, acc[i][0]);
                acc[i][1] = fmaf(a[i].y, b1.y, acc[i][1]);
                acc[i][2] = fmaf(a[i].y, b1.z, acc[i][2]);
                acc[i][3] = fmaf(a[i].y, b1.w, acc[i][3]);
            }
        }
    }

    // ---- epilogue: Q scale+store / permuted KV scatter ----
#pragma unroll
    for (int i = 0; i < 8; i++) {
        int row = row0 + mg + 16 * i;
        int b = row >> 9, n = row & 511;
#pragma unroll
        for (int j = 0; j < 4; j++) {
            int c = col0 + ng * 4 + j;
            if (c >= 240) continue;
            float v = acc[i][j];
            if (c < 192) {                       // Q path
                v = (v + bq[c]) * QSCALE;
                int head = c >> 5, d = c & 31;
                g_q[(((size_t)b * NH + head) * NTOK + n) * HD + d] = v;
            } else {                             // KV path: permuted scatter
                int c4 = c - 192;
                v = v + bkv[c4];
                int D = n >> 6, H = (n >> 3) & 7, W = n & 7;
                int p  = ((D >> 1) << 4) + ((H >> 1) << 2) + (W >> 1);
                int c2 = (H & 1) * 96 + (W & 1) * 48 + c4;
                int head = c2 >> 5, d = c2 & 31;
                size_t dst = (((size_t)b * NH + head) * PT + p) * HD + d;
                if ((D & 1) == 0) g_k[dst] = v;
                else              g_v[dst] = v;
            }
        }
    }
}

// ---------------- kernel 2: attention (1 thread = 1 query row) --------------
__global__ __launch_bounds__(128) void attn_kernel() {
    int bh = blockIdx.x;                 // b*6 + h
    int h  = bh % NH;
    int b  = bh / NH;
    int n  = blockIdx.y * 128 + threadIdx.x;

    __shared__ float4 k4[PT * 8];
    __shared__ float4 v4[PT * 8];
    const float4* gk = (const float4*)(g_k + (size_t)bh * PT * HD);
    const float4* gv = (const float4*)(g_v + (size_t)bh * PT * HD);
    for (int i = threadIdx.x; i < PT * 8; i += 128) { k4[i] = gk[i]; v4[i] = gv[i]; }

    float4 q[8];
    const float4* gq = (const float4*)(g_q + ((size_t)bh * NTOK + n) * HD);
#pragma unroll
    for (int i = 0; i < 8; i++) q[i] = gq[i];

    float sc[64];
    const float4* brow = (const float4*)(g_bias + ((size_t)h * NTOK + n) * PT);
#pragma unroll
    for (int i = 0; i < 16; i++) {
        float4 bb = brow[i];
        sc[4 * i + 0] = bb.x; sc[4 * i + 1] = bb.y;
        sc[4 * i + 2] = bb.z; sc[4 * i + 3] = bb.w;
    }
    __syncthreads();

    float m = -1e30f;
#pragma unroll
    for (int p = 0; p < 64; p++) {
        float s = sc[p];
#pragma unroll
        for (int d = 0; d < 8; d++) {
            float4 kk = k4[p * 8 + d];           // broadcast LDS.128
            s += q[d].x * kk.x + q[d].y * kk.y + q[d].z * kk.z + q[d].w * kk.w;
        }
        sc[p] = s;
        m = fmaxf(m, s);
    }
    float sum = 0.f;
#pragma unroll
    for (int p = 0; p < 64; p++) { float e = __expf(sc[p] - m); sc[p] = e; sum += e; }

    float4 acc[8];
#pragma unroll
    for (int d = 0; d < 8; d++) acc[d] = make_float4(0.f, 0.f, 0.f, 0.f);
#pragma unroll
    for (int p = 0; p < 64; p++) {
        float pr = sc[p];
#pragma unroll
        for (int d = 0; d < 8; d++) {
            float4 vv = v4[p * 8 + d];           // broadcast LDS.128
            acc[d].x = fmaf(pr, vv.x, acc[d].x);
            acc[d].y = fmaf(pr, vv.y, acc[d].y);
            acc[d].z = fmaf(pr, vv.z, acc[d].z);
            acc[d].w = fmaf(pr, vv.w, acc[d].w);
        }
    }
    float inv = 1.f / sum;
    float4* orow = (float4*)(g_att + ((size_t)(b * NTOK + n)) * DIMC + h * HD);
#pragma unroll
    for (int d = 0; d < 8; d++) {
        acc[d].x *= inv; acc[d].y *= inv; acc[d].z *= inv; acc[d].w *= inv;
        orow[d] = acc[d];
    }
}

// ---------------- kernel 3: output projection -------------------------------
__global__ __launch_bounds__(256) void proj_gemm(
    const float* __restrict__ wproj, const float* __restrict__ bproj,
    float* __restrict__ out)
{
    constexpr int KT = 24;
    __shared__ float x_sh[128][28];
    __shared__ float w_sh[KT][68];

    int tid = threadIdx.x;
    int mg  = tid >> 4;
    int ng  = tid & 15;
    int row0 = blockIdx.x * 128;
    int col0 = blockIdx.y * 64;

    float acc[8][4];
#pragma unroll
    for (int i = 0; i < 8; i++)
#pragma unroll
        for (int j = 0; j < 4; j++) acc[i][j] = 0.f;

    for (int kt = 0; kt < 8; kt++) {
        int k0 = kt * KT;
        if (kt) __syncthreads();

#pragma unroll
        for (int i = 0; i < 3; i++) {
            int f = tid + i * 256;
            int r = f / 6, q = f % 6;
            float4 v = *(const float4*)(g_att + (size_t)(row0 + r) * DIMC + k0 + q * 4);
            *(float4*)&x_sh[r][q * 4] = v;
        }
#pragma unroll
        for (int i = 0; i < 2; i++) {
            int f = tid + i * 256;
            if (f < 384) {
                int k = f >> 4, cq = f & 15;
                float4 v = *(const float4*)(wproj + (size_t)(k0 + k) * 192 + col0 + cq * 4);
                *(float4*)&w_sh[k][cq * 4] = v;
            }
        }
        __syncthreads();

        for (int s = 0; s < 12; s++) {
            float2 a[8];
#pragma unroll
            for (int i = 0; i < 8; i++)
                a[i] = *(const float2*)&x_sh[mg + 16 * i][s * 2];
            float4 b0 = *(const float4*)&w_sh[s * 2][ng * 4];
            float4 b1 = *(const float4*)&w_sh[s * 2 + 1][ng * 4];
#pragma unroll
            for (int i = 0; i < 8; i++) {
                acc[i][0] = fmaf(a[i].x, b0.x, acc[i][0]);
                acc[i][1] = fmaf(a[i].x, b0.y, acc[i][1]);
                acc[i][2] = fmaf(a[i].x, b0.z, acc[i][2]);
                acc[i][3] = fmaf(a[i].x, b0.w, acc[i][3]);
                acc[i][0] = fmaf(a[i].y, b1.x, acc[i][0]);
                acc[i][1] = fmaf(a[i].y, b1.y, acc[i][1]);
                acc[i][2] = fmaf(a[i].y, b1.z, acc[i][2]);
                acc[i][3] = fmaf(a[i].y, b1.w, acc[i][3]);
            }
        }
    }

    // ---- epilogue: vectorized store with bias ----
    int cb = col0 + ng * 4;
    float4 bias = *(const float4*)(bproj + cb);
#pragma unroll
    for (int i = 0; i < 8; i++) {
        size_t row = row0 + mg + 16 * i;
        float4 o;
        o.x = acc[i][0] + bias.x;
        o.y = acc[i][1] + bias.y;
        o.z = acc[i][2] + bias.z;
        o.w = acc[i][3] + bias.w;
        *(float4*)(out + row * DIMC + cb) = o;
    }
}

// ---------------- launch ----------------------------------------------------
extern "C" void kernel_launch(void* const* d_in, const int* in_sizes, int n_in,
                              void* d_out, int out_size) {
    const float* x     = (const float*)d_in[0];
    const float* wq    = (const float*)d_in[1];
    const float* bq    = (const float*)d_in[2];
    const float* wkv   = (const float*)d_in[3];
    const float* bkv   = (const float*)d_in[4];
    const float* table = (const float*)d_in[5];
    const float* wproj = (const float*)d_in[6];
    const float* bproj = (const float*)d_in[7];
    const int*   rpi   = (const int*)d_in[8];
    float* out = (float*)d_out;

    bias_gather<<<(NH * NTOK * PT + 255) / 256, 256>>>(table, rpi);
    qkv_gemm<<<dim3(2048, 4), 256>>>(x, wq, bq, wkv, bkv);
    attn_kernel<<<dim3(BW * NH, 4), 128>>>();
    proj_gemm<<<dim3(2048, 3), 256>>>(wproj, bproj, out);
}

// round 12
// speedup vs baseline: 1.2709x; 1.0005x over previous
#include <cuda_runtime.h>

#define BW    512      // batch windows
#define NTOK  512      // query tokens per window
#define DIMC  192
#define NH    6
#define HD    32
#define PT    64       // permuted kv tokens per window
#define QSCALE 0.17677669529663687f   // 1/sqrt(32)

// ---------------- scratch (static device globals; no runtime allocation) ----
__device__ float g_q[(size_t)BW * NH * NTOK * HD];    // [b][h][n][d]
__device__ float g_k[(size_t)BW * NH * PT * HD];      // [b][h][p][d]
__device__ float g_v[(size_t)BW * NH * PT * HD];      // [b][h][p][d]
__device__ float g_bias[NH * NTOK * PT];              // [h][n][p]
__device__ float g_att[(size_t)BW * NTOK * DIMC];     // [b][n][h*32+d]

// ---------------- kernel 0: gather relative-position bias -------------------
__global__ void bias_gather(const float* __restrict__ table,
                            const int* __restrict__ rpi) {
    int idx = blockIdx.x * 256 + threadIdx.x;
    if (idx >= NH * NTOK * PT) return;
    int h = idx / (NTOK * PT);
    int r = idx - h * (NTOK * PT);            // n*64 + p
    g_bias[idx] = table[rpi[r] * NH + h];
}

// ---------------- kernel 1: fused QKV projection + permuted scatter ---------
// y[262144 x 240] = x[262144 x 192] @ [wq | wkv]
// block 128x64 (grid.y=4, cols >=240 masked), 256 threads, thread tile 8x4.
// KT=24, A frags as float2 (2-kk steps): regs ~70 -> 3 blocks/SM (reg-file
// boundary at 85 regs); smem 20.8KB/block so smem never binds.
__global__ __launch_bounds__(256) void qkv_gemm(
    const float* __restrict__ x,
    const float* __restrict__ wq, const float* __restrict__ bq,
    const float* __restrict__ wkv, const float* __restrict__ bkv)
{
    constexpr int KT = 24;
    __shared__ float x_sh[128][28];   // [m][k], pitch 28 (7 quads, odd -> cf)
    __shared__ float w_sh[KT][68];    // [k][n], pitch 68 (17 quads)

    int tid = threadIdx.x;
    int mg  = tid >> 4;               // 0..15: thread rows = mg + 16*i
    int ng  = tid & 15;               // 0..15: thread cols = ng*4 .. +3
    int row0 = blockIdx.x * 128;
    int col0 = blockIdx.y * 64;

    float acc[8][4];
#pragma unroll
    for (int i = 0; i < 8; i++)
#pragma unroll
        for (int j = 0; j < 4; j++) acc[i][j] = 0.f;

    for (int kt = 0; kt < 8; kt++) {
        int k0 = kt * KT;
        if (kt) __syncthreads();

        // ---- X tile: 128 x 24 = 768 float4, 3 per thread -------------------
#pragma unroll
        for (int i = 0; i < 3; i++) {
            int f = tid + i * 256;
            int r = f / 6, q = f % 6;
            float4 v = *(const float4*)(x + (size_t)(row0 + r) * DIMC + k0 + q * 4);
            *(float4*)&x_sh[r][q * 4] = v;
        }
        // ---- W tile: 24 k x 64 n = 384 float4 ------------------------------
#pragma unroll
        for (int i = 0; i < 2; i++) {
            int f = tid + i * 256;
            if (f < 384) {
                int k = f >> 4, cq = f & 15;
                float4 v;
                if (col0 < 192) {                // pure-Q column blocks
                    v = *(const float4*)(wq + (size_t)(k0 + k) * 192 + col0 + cq * 4);
                } else {                         // KV block (cols 192..255)
                    if (cq < 12)
                        v = *(const float4*)(wkv + (size_t)(k0 + k) * 48 + cq * 4);
                    else
                        v = make_float4(0.f, 0.f, 0.f, 0.f);
                }
                *(float4*)&w_sh[k][cq * 4] = v;
            }
        }
        __syncthreads();

        // ---- mainloop: 12 x (2-kk) steps ----
        for (int s = 0; s < 12; s++) {
            float2 a[8];
#pragma unroll
            for (int i = 0; i < 8; i++)
                a[i] = *(const float2*)&x_sh[mg + 16 * i][s * 2];
            float4 b0 = *(const float4*)&w_sh[s * 2][ng * 4];
            float4 b1 = *(const float4*)&w_sh[s * 2 + 1][ng * 4];
#pragma unroll
            for (int i = 0; i < 8; i++) {
                acc[i][0] = fmaf(a[i].x, b0.x, acc[i][0]);
                acc[i][1] = fmaf(a[i].x, b0.y, acc[i][1]);
                acc[i][2] = fmaf(a[i].x, b0.z, acc[i][2]);
                acc[i][3] = fmaf(a[i].x, b0.w, acc[i][3]);
                acc[i][0] = fmaf(a[i].y, b1.x, acc[i][0]);
                acc[i][1] = fmaf(a[i].y, b1.y, acc[i][1]);
                acc[i][2] = fmaf(a[i].y, b1.z, acc[i][2]);
                acc[i][3] = fmaf(a[i].y, b1.w, acc[i][3]);
            }
        }
    }

    // ---- epilogue: Q scale+store / permuted KV scatter ----
#pragma unroll
    for (int i = 0; i < 8; i++) {
        int row = row0 + mg + 16 * i;
        int b = row >> 9, n = row & 511;
#pragma unroll
        for (int j = 0; j < 4; j++) {
            int c = col0 + ng * 4 + j;
            if (c >= 240) continue;
            float v = acc[i][j];
            if (c < 192) {                       // Q path
                v = (v + bq[c]) * QSCALE;
                int head = c >> 5, d = c & 31;
                g_q[(((size_t)b * NH + head) * NTOK + n) * HD + d] = v;
            } else {                             // KV path: permuted scatter
                int c4 = c - 192;
                v = v + bkv[c4];
                int D = n >> 6, H = (n >> 3) & 7, W = n & 7;
                int p  = ((D >> 1) << 4) + ((H >> 1) << 2) + (W >> 1);
                int c2 = (H & 1) * 96 + (W & 1) * 48 + c4;
                int head = c2 >> 5, d = c2 & 31;
                size_t dst = (((size_t)b * NH + head) * PT + p) * HD + d;
                if ((D & 1) == 0) g_k[dst] = v;
                else              g_v[dst] = v;
            }
        }
    }
}

// ---------------- kernel 2: attention (1 thread = 1 query row) --------------
__global__ __launch_bounds__(128) void attn_kernel() {
    int bh = blockIdx.x;                 // b*6 + h
    int h  = bh % NH;
    int b  = bh / NH;
    int n  = blockIdx.y * 128 + threadIdx.x;

    __shared__ float4 k4[PT * 8];
    __shared__ float4 v4[PT * 8];
    const float4* gk = (const float4*)(g_k + (size_t)bh * PT * HD);
    const float4* gv = (const float4*)(g_v + (size_t)bh * PT * HD);
    for (int i = threadIdx.x; i < PT * 8; i += 128) { k4[i] = gk[i]; v4[i] = gv[i]; }

    float4 q[8];
    const float4* gq = (const float4*)(g_q + ((size_t)bh * NTOK + n) * HD);
#pragma unroll
    for (int i = 0; i < 8; i++) q[i] = gq[i];

    float sc[64];
    const float4* brow = (const float4*)(g_bias + ((size_t)h * NTOK + n) * PT);
#pragma unroll
    for (int i = 0; i < 16; i++) {
        float4 bb = brow[i];
        sc[4 * i + 0] = bb.x; sc[4 * i + 1] = bb.y;
        sc[4 * i + 2] = bb.z; sc[4 * i + 3] = bb.w;
    }
    __syncthreads();

    float m = -1e30f;
#pragma unroll
    for (int p = 0; p < 64; p++) {
        float s = sc[p];
#pragma unroll
        for (int d = 0; d < 8; d++) {
            float4 kk = k4[p * 8 + d];           // broadcast LDS.128
            s += q[d].x * kk.x + q[d].y * kk.y + q[d].z * kk.z + q[d].w * kk.w;
        }
        sc[p] = s;
        m = fmaxf(m, s);
    }
    float sum = 0.f;
#pragma unroll
    for (int p = 0; p < 64; p++) { float e = __expf(sc[p] - m); sc[p] = e; sum += e; }

    float4 acc[8];
#pragma unroll
    for (int d = 0; d < 8; d++) acc[d] = make_float4(0.f, 0.f, 0.f, 0.f);
#pragma unroll
    for (int p = 0; p < 64; p++) {
        float pr = sc[p];
#pragma unroll
        for (int d = 0; d < 8; d++) {
            float4 vv = v4[p * 8 + d];           // broadcast LDS.128
            acc[d].x = fmaf(pr, vv.x, acc[d].x);
            acc[d].y = fmaf(pr, vv.y, acc[d].y);
            acc[d].z = fmaf(pr, vv.z, acc[d].z);
            acc[d].w = fmaf(pr, vv.w, acc[d].w);
        }
    }
    float inv = 1.f / sum;
    float4* orow = (float4*)(g_att + ((size_t)(b * NTOK + n)) * DIMC + h * HD);
#pragma unroll
    for (int d = 0; d < 8; d++) {
        acc[d].x *= inv; acc[d].y *= inv; acc[d].z *= inv; acc[d].w *= inv;
        orow[d] = acc[d];
    }
}

// ---------------- kernel 3: output projection -------------------------------
__global__ __launch_bounds__(256) void proj_gemm(
    const float* __restrict__ wproj, const float* __restrict__ bproj,
    float* __restrict__ out)
{
    constexpr int KT = 24;
    __shared__ float x_sh[128][28];
    __shared__ float w_sh[KT][68];

    int tid = threadIdx.x;
    int mg  = tid >> 4;
    int ng  = tid & 15;
    int row0 = blockIdx.x * 128;
    int col0 = blockIdx.y * 64;

    float acc[8][4];
#pragma unroll
    for (int i = 0; i < 8; i++)
#pragma unroll
        for (int j = 0; j < 4; j++) acc[i][j] = 0.f;

    for (int kt = 0; kt < 8; kt++) {
        int k0 = kt * KT;
        if (kt) __syncthreads();

#pragma unroll
        for (int i = 0; i < 3; i++) {
            int f = tid + i * 256;
            int r = f / 6, q = f % 6;
            float4 v = *(const float4*)(g_att + (size_t)(row0 + r) * DIMC + k0 + q * 4);
            *(float4*)&x_sh[r][q * 4] = v;
        }
#pragma unroll
        for (int i = 0; i < 2; i++) {
            int f = tid + i * 256;
            if (f < 384) {
                int k = f >> 4, cq = f & 15;
                float4 v = *(const float4*)(wproj + (size_t)(k0 + k) * 192 + col0 + cq * 4);
                *(float4*)&w_sh[k][cq * 4] = v;
            }
        }
        __syncthreads();

        for (int s = 0; s < 12; s++) {
            float2 a[8];
#pragma unroll
            for (int i = 0; i < 8; i++)
                a[i] = *(const float2*)&x_sh[mg + 16 * i][s * 2];
            float4 b0 = *(const float4*)&w_sh[s * 2][ng * 4];
            float4 b1 = *(const float4*)&w_sh[s * 2 + 1][ng * 4];
#pragma unroll
            for (int i = 0; i < 8; i++) {
                acc[i][0] = fmaf(a[i].x, b0.x, acc[i][0]);
                acc[i][1] = fmaf(a[i].x, b0.y, acc[i][1]);
                acc[i][2] = fmaf(a[i].x, b0.z, acc[i][2]);
                acc[i][3] = fmaf(a[i].x, b0.w, acc[i][3]);
                acc[i][0] = fmaf(a[i].y, b1.x, acc[i][0]);
                acc[i][1] = fmaf(a[i].y, b1.y, acc[i][1]);
                acc[i][2] = fmaf(a[i].y, b1.z, acc[i][2]);
                acc[i][3] = fmaf(a[i].y, b1.w, acc[i][3]);
            }
        }
    }

    // ---- epilogue: vectorized store with bias ----
    int cb = col0 + ng * 4;
    float4 bias = *(const float4*)(bproj + cb);
#pragma unroll
    for (int i = 0; i < 8; i++) {
        size_t row = row0 + mg + 16 * i;
        float4 o;
        o.x = acc[i][0] + bias.x;
        o.y = acc[i][1] + bias.y;
        o.z = acc[i][2] + bias.z;
        o.w = acc[i][3] + bias.w;
        *(float4*)(out + row * DIMC + cb) = o;
    }
}

// ---------------- launch ----------------------------------------------------
extern "C" void kernel_launch(void* const* d_in, const int* in_sizes, int n_in,
                              void* d_out, int out_size) {
    const float* x     = (const float*)d_in[0];
    const float* wq    = (const float*)d_in[1];
    const float* bq    = (const float*)d_in[2];
    const float* wkv   = (const float*)d_in[3];
    const float* bkv   = (const float*)d_in[4];
    const float* table = (const float*)d_in[5];
    const float* wproj = (const float*)d_in[6];
    const float* bproj = (const float*)d_in[7];
    const int*   rpi   = (const int*)d_in[8];
    float* out = (float*)d_out;

    bias_gather<<<(NH * NTOK * PT + 255) / 256, 256>>>(table, rpi);
    qkv_gemm<<<dim3(2048, 4), 256>>>(x, wq, bq, wkv, bkv);
    attn_kernel<<<dim3(BW * NH, 4), 128>>>();
    proj_gemm<<<dim3(2048, 3), 256>>>(wproj, bproj, out);
}